// round 9
// baseline (speedup 1.0000x reference)
#include <cuda_runtime.h>
#include <cuda_bf16.h>
#include <cstdint>

#define NNODES 100000
#define NEDGES 1000000
#define HDIM   64
#define ODIM   16
#define NREL   90
#define NBASES 8
#define KDIM   512   // NBASES*HDIM

// ---------------- scratch (device globals; no allocations allowed) ----------
__device__ __align__(16) float g_h0[(size_t)NNODES * HDIM];    // ping
__device__ __align__(16) float g_h1[(size_t)NNODES * HDIM];    // pong
__device__ int g_deg[NNODES];
__device__ int g_cursor[NNODES];
__device__ int g_rowptr[NNODES + 1];
__device__ unsigned long long g_packed[NEDGES];                // (norm<<32)|(etype<<17)|src
__device__ __align__(16) __nv_bfloat16 g_Whi[3][KDIM * 64];    // padded to 64 cols
__device__ __align__(16) __nv_bfloat16 g_Wlo[3][KDIM * 64];

// ---------------- preprocessing kernels -------------------------------------
__global__ void zero_kernel() {
    int i = blockIdx.x * blockDim.x + threadIdx.x;
    if (i < NNODES) { g_deg[i] = 0; g_cursor[i] = 0; }
}

__global__ void hist_kernel(const int* __restrict__ dst) {
    int i = blockIdx.x * blockDim.x + threadIdx.x;
    if (i < NEDGES) atomicAdd(&g_deg[dst[i]], 1);
}

__global__ void scan_kernel() {
    __shared__ int wsum[32];
    __shared__ int carry;
    int t = threadIdx.x;
    if (t == 0) carry = 0;
    __syncthreads();
    for (int base = 0; base < NNODES; base += 1024) {
        int i = base + t;
        int v = (i < NNODES) ? g_deg[i] : 0;
        int x = v;
        #pragma unroll
        for (int o = 1; o < 32; o <<= 1) {
            int y = __shfl_up_sync(0xffffffffu, x, o);
            if ((t & 31) >= o) x += y;
        }
        if ((t & 31) == 31) wsum[t >> 5] = x;
        __syncthreads();
        if (t < 32) {
            int s = wsum[t];
            #pragma unroll
            for (int o = 1; o < 32; o <<= 1) {
                int y = __shfl_up_sync(0xffffffffu, s, o);
                if (t >= o) s += y;
            }
            wsum[t] = s;
        }
        __syncthreads();
        int pre = (t >= 32) ? wsum[(t >> 5) - 1] : 0;
        int incl = x + pre;
        if (i < NNODES) g_rowptr[i] = carry + incl - v;   // exclusive
        int total = wsum[31];
        __syncthreads();
        if (t == 0) carry += total;
        __syncthreads();
    }
    if (t == 0) g_rowptr[NNODES] = carry;
}

__global__ void scatter_kernel(const int* __restrict__ src, const int* __restrict__ dst,
                               const int* __restrict__ etype, const float* __restrict__ norm) {
    int i = blockIdx.x * blockDim.x + threadIdx.x;
    if (i >= NEDGES) return;
    int d = dst[i];
    int pos = g_rowptr[d] + atomicAdd(&g_cursor[d], 1);
    unsigned lo = (unsigned)src[i] | ((unsigned)etype[i] << 17);
    g_packed[pos] = ((unsigned long long)__float_as_uint(norm[i]) << 32) | (unsigned long long)lo;
}

// Convert layer weight matrices to bf16 hi/lo split, padded to 64 output cols.
__global__ void wconv_kernel(const float* __restrict__ b0, const float* __restrict__ b1,
                             const float* __restrict__ b2) {
    int i = blockIdx.x * blockDim.x + threadIdx.x;
    if (i >= 3 * KDIM * 64) return;
    int layer = i / (KDIM * 64);
    int r = i % (KDIM * 64);
    int k = r >> 6, j = r & 63;
    float v;
    if (layer == 0)      v = b0[k * 64 + j];
    else if (layer == 1) v = b1[k * 64 + j];
    else                 v = (j < ODIM) ? b2[k * ODIM + j] : 0.0f;
    __nv_bfloat16 hi = __float2bfloat16(v);
    __nv_bfloat16 lo = __float2bfloat16(v - __bfloat162float(hi));
    g_Whi[layer][r] = hi;
    g_Wlo[layer][r] = lo;
}

// ---------------- fused layer: agg (registers) -> smem bf16 -> MMA ----------
__device__ __forceinline__ uint32_t swz(uint32_t o) { return o ^ ((o >> 3) & 0x70); }

__device__ __forceinline__ uint32_t pack2(__nv_bfloat16 a, __nv_bfloat16 b) {
    __nv_bfloat162 t = __halves2bfloat162(a, b);   // a -> low half (lower address)
    return *reinterpret_cast<uint32_t*>(&t);
}

__device__ __forceinline__ void ldsm4(uint32_t* r, uint32_t addr) {
    asm volatile("ldmatrix.sync.aligned.m8n8.x4.shared.b16 {%0,%1,%2,%3}, [%4];"
                 : "=r"(r[0]), "=r"(r[1]), "=r"(r[2]), "=r"(r[3]) : "r"(addr));
}
__device__ __forceinline__ void ldsm4t(uint32_t* r, uint32_t addr) {
    asm volatile("ldmatrix.sync.aligned.m8n8.x4.trans.shared.b16 {%0,%1,%2,%3}, [%4];"
                 : "=r"(r[0]), "=r"(r[1]), "=r"(r[2]), "=r"(r[3]) : "r"(addr));
}
__device__ __forceinline__ void mma16816(float* d, const uint32_t* a, const uint32_t* b) {
    asm volatile("mma.sync.aligned.m16n8k16.row.col.f32.bf16.bf16.f32 "
                 "{%0,%1,%2,%3}, {%4,%5,%6,%7}, {%8,%9}, {%0,%1,%2,%3};"
                 : "+f"(d[0]), "+f"(d[1]), "+f"(d[2]), "+f"(d[3])
                 : "r"(a[0]), "r"(a[1]), "r"(a[2]), "r"(a[3]), "r"(b[0]), "r"(b[1]));
}
__device__ __forceinline__ void cp16(uint32_t dst, const void* src) {
    asm volatile("cp.async.cg.shared.global [%0], [%1], 16;" :: "r"(dst), "l"(src));
}
__device__ __forceinline__ void cp_commit() {
    asm volatile("cp.async.commit_group;");
}
template <int N>
__device__ __forceinline__ void cp_wait() {
    asm volatile("cp.async.wait_group %0;" :: "n"(N));
}

// packed f32x2 helpers (sm_103a)
__device__ __forceinline__ unsigned long long pk_f32x2(float lo, float hi) {
    unsigned long long r;
    asm("mov.b64 %0, {%1, %2};" : "=l"(r) : "f"(lo), "f"(hi));
    return r;
}
__device__ __forceinline__ void unpk_f32x2(float& lo, float& hi, unsigned long long v) {
    asm("mov.b64 {%0, %1}, %2;" : "=f"(lo), "=f"(hi) : "l"(v));
}
__device__ __forceinline__ unsigned long long mul_f32x2(unsigned long long a, unsigned long long b) {
    unsigned long long r;
    asm("mul.rn.f32x2 %0, %1, %2;" : "=l"(r) : "l"(a), "l"(b));
    return r;
}
__device__ __forceinline__ void fma_f32x2(unsigned long long& d, unsigned long long a,
                                          unsigned long long b) {
    asm("fma.rn.f32x2 %0, %1, %2, %0;" : "+l"(d) : "l"(a), "l"(b));
}

// smem layout (bytes):
//   Ah: [0, 32768)         32 rows x 512 bf16, chunked: 8 chunks of [32x64], chunk stride 4096,
//                          elem (row,col) at chunk*4096 + swz(row*128 + col*2)
//   Al: [32768, 65536)
//   B stages: [65536, 98304)   stage s (0/1): Bh at 65536+s*16384, Bl at +8192
//                          elem (krow,n) at swz(krow*128 + n*2)
//   cs2: [98304, 104064)   90*8 duplicated f32x2 coeff pairs (8B each)
//   ctr: [104064, 104068)  dynamic node counter
#define SM_AH 0
#define SM_AL 32768
#define SM_B  65536
#define SM_CS 98304
#define SM_CTR 104064
#define SM_TOTAL 104080

extern __shared__ char smem_raw[];

#define EB 8   // edge batch (MLP depth)

template <bool RELU, int OCOLS>
__global__ void __launch_bounds__(256) fused_layer_kernel(
    const float* __restrict__ x, const float* __restrict__ coeff,
    int layer, const float* __restrict__ bias, float* __restrict__ out) {

    const __nv_bfloat16* Whi = g_Whi[layer];
    const __nv_bfloat16* Wlo = g_Wlo[layer];

    char* sm = smem_raw;
    uint32_t sm_u = (uint32_t)__cvta_generic_to_shared(sm);
    unsigned long long* cs2 = reinterpret_cast<unsigned long long*>(sm + SM_CS);
    int* ctr = reinterpret_cast<int*>(sm + SM_CTR);

    int tid = threadIdx.x;
    int wid = tid >> 5, lane = tid & 31;
    int tile0 = blockIdx.x * 32;

    // duplicated coeff pairs -> smem: cs2[r*8+b] = (c, c) as f32x2
    for (int i = tid; i < NREL * NBASES; i += 256) {
        float c = coeff[i];
        cs2[i] = pk_f32x2(c, c);
    }
    if (tid == 0) *ctr = 0;

    // Prefetch B chunk 0 (both planes) into stage 0 while edge phase runs.
    {
        #pragma unroll
        for (int it = 0; it < 4; it++) {
            int u = it * 256 + tid;            // 1024 16B units: 512 hi + 512 lo
            int plane = u >> 9, v = u & 511;
            int row = v >> 3, g = v & 7;
            uint32_t dstb = sm_u + SM_B + plane * 8192 + swz((uint32_t)(row * 128 + g * 16));
            const char* srcb = reinterpret_cast<const char*>(plane ? Wlo : Whi) + row * 128 + g * 16;
            cp16(dstb, srcb);
        }
        cp_commit();
    }
    __syncthreads();   // cs2 + ctr visible

    // ---- edge phase: warps pull nodes dynamically (load balance) ----
    // Lane owns features {2*lane, 2*lane+1}. Batch of EB edges: EB packed loads,
    // then EB independent gathers (MLP=EB), then packed-f32x2 FMAs (8 per edge).
    for (;;) {
        int rt;
        if (lane == 0) rt = atomicAdd(ctr, 1);
        rt = __shfl_sync(0xffffffffu, rt, 0);
        if (rt >= 32) break;
        int n = tile0 + rt;                    // grid sized so n < NNODES always
        unsigned long long acc2[8];            // (feat 2*lane, 2*lane+1) per basis
        #pragma unroll
        for (int k = 0; k < 8; k++) acc2[k] = 0ULL;
        int s = g_rowptr[n], e = g_rowptr[n + 1];
        #pragma unroll 1
        for (int i = s; i < e; i += EB) {
            unsigned long long p[EB];
            float2 xv[EB];
            #pragma unroll
            for (int k = 0; k < EB; k++)
                p[k] = (i + k < e) ? __ldg(&g_packed[i + k]) : 0ULL;   // p=0 -> nrm=0
            #pragma unroll
            for (int k = 0; k < EB; k++) {
                int srcn = (unsigned)p[k] & 0x1FFFF;
                xv[k] = __ldg(reinterpret_cast<const float2*>(x + (size_t)srcn * 64) + lane);
            }
            #pragma unroll
            for (int k = 0; k < EB; k++) {
                int rel = ((unsigned)p[k] >> 17) & 0x7F;
                float nrm = __uint_as_float((unsigned)(p[k] >> 32));
                unsigned long long x2 = mul_f32x2(pk_f32x2(xv[k].x, xv[k].y),
                                                 pk_f32x2(nrm, nrm));
                const unsigned long long* c2 = cs2 + rel * 8;   // broadcast, conflict-free
                ulonglong2 cA = *reinterpret_cast<const ulonglong2*>(c2);
                ulonglong2 cB = *reinterpret_cast<const ulonglong2*>(c2 + 2);
                ulonglong2 cC = *reinterpret_cast<const ulonglong2*>(c2 + 4);
                ulonglong2 cD = *reinterpret_cast<const ulonglong2*>(c2 + 6);
                fma_f32x2(acc2[0], cA.x, x2);
                fma_f32x2(acc2[1], cA.y, x2);
                fma_f32x2(acc2[2], cB.x, x2);
                fma_f32x2(acc2[3], cB.y, x2);
                fma_f32x2(acc2[4], cC.x, x2);
                fma_f32x2(acc2[5], cC.y, x2);
                fma_f32x2(acc2[6], cD.x, x2);
                fma_f32x2(acc2[7], cD.y, x2);
            }
        }
        // convert to bf16 hi/lo, store pairs (features 2*lane, 2*lane+1 of basis b)
        #pragma unroll
        for (int b = 0; b < 8; b++) {
            float va, vb;
            unpk_f32x2(va, vb, acc2[b]);
            __nv_bfloat16 ha = __float2bfloat16(va);
            __nv_bfloat16 la = __float2bfloat16(va - __bfloat162float(ha));
            __nv_bfloat16 hb = __float2bfloat16(vb);
            __nv_bfloat16 lb = __float2bfloat16(vb - __bfloat162float(hb));
            uint32_t o = (uint32_t)(b * 4096) + swz((uint32_t)(rt * 128 + lane * 4));
            *reinterpret_cast<uint32_t*>(sm + SM_AH + o) = pack2(ha, hb);
            *reinterpret_cast<uint32_t*>(sm + SM_AL + o) = pack2(la, lb);
        }
    }
    __syncthreads();   // A tile complete

    // ---- GEMM phase: [32 x 512] @ [512 x 64], warps 2x4 over 16x16 subtiles ----
    int wm = wid & 1, wn = wid >> 1;
    float facc[2][4];
    #pragma unroll
    for (int a = 0; a < 2; a++)
        #pragma unroll
        for (int b = 0; b < 4; b++) facc[a][b] = 0.0f;

    #pragma unroll 1
    for (int kc8 = 0; kc8 < 8; kc8++) {
        int stage = kc8 & 1;
        if (kc8 < 7) {   // prefetch next chunk into other stage
            int c = kc8 + 1, st = stage ^ 1;
            #pragma unroll
            for (int it = 0; it < 4; it++) {
                int u = it * 256 + tid;
                int plane = u >> 9, v = u & 511;
                int row = v >> 3, g = v & 7;
                uint32_t dstb = sm_u + SM_B + st * 16384 + plane * 8192 +
                                swz((uint32_t)(row * 128 + g * 16));
                const char* srcb = reinterpret_cast<const char*>(plane ? Wlo : Whi) +
                                   (size_t)(c * 64 + row) * 128 + g * 16;
                cp16(dstb, srcb);
            }
            cp_commit();
            cp_wait<1>();
        } else {
            cp_wait<0>();
        }
        __syncthreads();  // current stage data visible to all

        if (OCOLS == 64 || wn == 0) {
            uint32_t uBh = sm_u + SM_B + stage * 16384;
            uint32_t uBl = uBh + 8192;
            #pragma unroll
            for (int ks = 0; ks < 4; ks++) {
                uint32_t ah[4], al[4], bh[4], bl[4];
                int r = wm * 16 + (lane & 15);
                uint32_t oA = (uint32_t)(kc8 * 4096) +
                              swz((uint32_t)(r * 128 + ks * 32 + (lane >> 4) * 16));
                ldsm4(ah, sm_u + SM_AH + oA);
                ldsm4(al, sm_u + SM_AL + oA);
                int mat = lane >> 3, sub = lane & 7;
                int krow = ks * 16 + (mat & 1) * 8 + sub;
                int nb = wn * 16 + (mat >> 1) * 8;
                uint32_t oB = swz((uint32_t)(krow * 128 + nb * 2));
                ldsm4t(bh, uBh + oB);
                ldsm4t(bl, uBl + oB);
                #pragma unroll
                for (int nt = 0; nt < 2; nt++) {
                    float* d = facc[nt];
                    mma16816(d, ah, &bh[nt * 2]);   // hi*hi
                    mma16816(d, ah, &bl[nt * 2]);   // hi*lo
                    mma16816(d, al, &bh[nt * 2]);   // lo*hi
                }
            }
        }
        __syncthreads();  // done reading this stage before it gets overwritten
    }

    // ---- epilogue ----
    #pragma unroll
    for (int nt = 0; nt < 2; nt++)
        #pragma unroll
        for (int r = 0; r < 4; r++) {
            int row = tile0 + wm * 16 + (lane >> 2) + ((r >> 1) ? 8 : 0);
            int col = wn * 16 + nt * 8 + (lane & 3) * 2 + (r & 1);
            if ((OCOLS == 64 || wn == 0) && col < OCOLS) {
                float v = facc[nt][r] + bias[col];
                if (RELU) v = fmaxf(v, 0.0f);
                out[(size_t)row * OCOLS + col] = v;
            }
        }
}

// ---------------- launcher ---------------------------------------------------
extern "C" void kernel_launch(void* const* d_in, const int* in_sizes, int n_in,
                              void* d_out, int out_size) {
    const float* feats  = (const float*)d_in[0];
    const float* coeff0 = (const float*)d_in[1];
    const float* bases0 = (const float*)d_in[2];
    const float* bias0  = (const float*)d_in[3];
    const float* coeff1 = (const float*)d_in[4];
    const float* bases1 = (const float*)d_in[5];
    const float* bias1  = (const float*)d_in[6];
    const float* coeff2 = (const float*)d_in[7];
    const float* bases2 = (const float*)d_in[8];
    const float* bias2  = (const float*)d_in[9];
    const int*   src    = (const int*)d_in[10];
    const int*   dst    = (const int*)d_in[11];
    const int*   etype  = (const int*)d_in[12];
    const float* norm   = (const float*)d_in[13];
    float* out = (float*)d_out;

    cudaFuncSetAttribute(fused_layer_kernel<true, 64>,
                         cudaFuncAttributeMaxDynamicSharedMemorySize, SM_TOTAL);
    cudaFuncSetAttribute(fused_layer_kernel<false, 16>,
                         cudaFuncAttributeMaxDynamicSharedMemorySize, SM_TOTAL);

    // Graph preprocessing (CSR by dst) + weight conversion
    zero_kernel<<<(NNODES + 255) / 256, 256>>>();
    hist_kernel<<<(NEDGES + 255) / 256, 256>>>(dst);
    scan_kernel<<<1, 1024>>>();
    scatter_kernel<<<(NEDGES + 255) / 256, 256>>>(src, dst, etype, norm);
    wconv_kernel<<<(3 * KDIM * 64 + 255) / 256, 256>>>(bases0, bases1, bases2);

    // pointers to ping-pong device globals (resolved at launch via symbol refs)
    float* h0;  cudaGetSymbolAddress((void**)&h0, g_h0);
    float* h1;  cudaGetSymbolAddress((void**)&h1, g_h1);

    const int GRID = NNODES / 32;   // 100000/32 = 3125, exact

    // Ping-pong buffers: fused kernels gather-read the previous layer's
    // activations while writing the current layer's — they MUST be distinct
    // (cross-block RAW hazard otherwise).
    fused_layer_kernel<true, 64><<<GRID, 256, SM_TOTAL>>>(feats, coeff0, 0, bias0, h0);
    fused_layer_kernel<true, 64><<<GRID, 256, SM_TOTAL>>>(h0,    coeff1, 1, bias1, h1);
    fused_layer_kernel<false, 16><<<GRID, 256, SM_TOTAL>>>(h1,   coeff2, 2, bias2, out);
}

// round 11
// speedup vs baseline: 1.2053x; 1.2053x over previous
#include <cuda_runtime.h>
#include <cuda_bf16.h>
#include <cstdint>

#define NNODES 100000
#define NEDGES 1000000
#define HDIM   64
#define ODIM   16
#define NREL   90
#define NBASES 8
#define KDIM   512   // NBASES*HDIM
#define NSCANB 98    // ceil(NNODES/1024)

// ---------------- scratch (device globals; no allocations allowed) ----------
__device__ __align__(16) float g_h0[(size_t)NNODES * HDIM];    // ping
__device__ __align__(16) float g_h1[(size_t)NNODES * HDIM];    // pong
__device__ int g_deg[NNODES];
__device__ int g_cursor[NNODES];
__device__ int g_rowptr[NNODES + 1];
__device__ int g_bsum[NSCANB];
__device__ unsigned long long g_packed[NEDGES];                // (norm<<32)|(etype<<17)|src
__device__ __align__(16) __nv_bfloat16 g_Whi[3][KDIM * 64];    // padded to 64 cols
__device__ __align__(16) __nv_bfloat16 g_Wlo[3][KDIM * 64];

// ---------------- preprocessing kernels -------------------------------------
__global__ void zero_kernel() {
    int i = blockIdx.x * blockDim.x + threadIdx.x;
    if (i < NNODES) { g_deg[i] = 0; g_cursor[i] = 0; }
}

__global__ void hist_kernel(const int* __restrict__ dst) {
    int i = blockIdx.x * blockDim.x + threadIdx.x;
    if (i < NEDGES) atomicAdd(&g_deg[dst[i]], 1);
}

// Multi-block scan, pass 1: per-block exclusive scan of 1024 degs + block sum.
__global__ void scan1_kernel() {
    __shared__ int wsum[32];
    int t = threadIdx.x;
    int i = blockIdx.x * 1024 + t;
    int v = (i < NNODES) ? g_deg[i] : 0;
    int x = v;
    #pragma unroll
    for (int o = 1; o < 32; o <<= 1) {
        int y = __shfl_up_sync(0xffffffffu, x, o);
        if ((t & 31) >= o) x += y;
    }
    if ((t & 31) == 31) wsum[t >> 5] = x;
    __syncthreads();
    if (t < 32) {
        int s = wsum[t];
        #pragma unroll
        for (int o = 1; o < 32; o <<= 1) {
            int y = __shfl_up_sync(0xffffffffu, s, o);
            if (t >= o) s += y;
        }
        wsum[t] = s;
    }
    __syncthreads();
    int pre = (t >= 32) ? wsum[(t >> 5) - 1] : 0;
    if (i < NNODES) g_rowptr[i] = pre + x - v;       // block-local exclusive
    if (t == 0) g_bsum[blockIdx.x] = wsum[31];
}

// Pass 2: exclusive scan of the 98 block sums (single small block); writes total.
__global__ void scan2_kernel() {
    __shared__ int wsum[4];
    int t = threadIdx.x;                              // 128 threads
    int v = (t < NSCANB) ? g_bsum[t] : 0;
    int x = v;
    #pragma unroll
    for (int o = 1; o < 32; o <<= 1) {
        int y = __shfl_up_sync(0xffffffffu, x, o);
        if ((t & 31) >= o) x += y;
    }
    if ((t & 31) == 31) wsum[t >> 5] = x;
    __syncthreads();
    if (t < 4) {
        int s = wsum[t];
        #pragma unroll
        for (int o = 1; o < 4; o <<= 1) {
            int y = __shfl_up_sync(0xfu, s, o);
            if (t >= o) s += y;
        }
        wsum[t] = s;
    }
    __syncthreads();
    int pre = (t >= 32) ? wsum[(t >> 5) - 1] : 0;
    if (t < NSCANB) g_bsum[t] = pre + x - v;          // exclusive block offset
    if (t == 0) g_rowptr[NNODES] = wsum[3];           // total = NEDGES
}

// Pass 3: add block offsets.
__global__ void scan3_kernel() {
    int i = blockIdx.x * blockDim.x + threadIdx.x;
    if (i < NNODES) g_rowptr[i] += g_bsum[i >> 10];
}

__global__ void scatter_kernel(const int* __restrict__ src, const int* __restrict__ dst,
                               const int* __restrict__ etype, const float* __restrict__ norm) {
    int i = blockIdx.x * blockDim.x + threadIdx.x;
    if (i >= NEDGES) return;
    int d = dst[i];
    int pos = g_rowptr[d] + atomicAdd(&g_cursor[d], 1);
    unsigned lo = (unsigned)src[i] | ((unsigned)etype[i] << 17);
    g_packed[pos] = ((unsigned long long)__float_as_uint(norm[i]) << 32) | (unsigned long long)lo;
}

// Convert layer weight matrices to bf16 hi/lo split, padded to 64 output cols.
__global__ void wconv_kernel(const float* __restrict__ b0, const float* __restrict__ b1,
                             const float* __restrict__ b2) {
    int i = blockIdx.x * blockDim.x + threadIdx.x;
    if (i >= 3 * KDIM * 64) return;
    int layer = i / (KDIM * 64);
    int r = i % (KDIM * 64);
    int k = r >> 6, j = r & 63;
    float v;
    if (layer == 0)      v = b0[k * 64 + j];
    else if (layer == 1) v = b1[k * 64 + j];
    else                 v = (j < ODIM) ? b2[k * ODIM + j] : 0.0f;
    __nv_bfloat16 hi = __float2bfloat16(v);
    __nv_bfloat16 lo = __float2bfloat16(v - __bfloat162float(hi));
    g_Whi[layer][r] = hi;
    g_Wlo[layer][r] = lo;
}

// ---------------- fused layer: agg (registers) -> smem bf16 -> MMA ----------
__device__ __forceinline__ uint32_t swz(uint32_t o) { return o ^ ((o >> 3) & 0x70); }

__device__ __forceinline__ uint32_t pack2(__nv_bfloat16 a, __nv_bfloat16 b) {
    __nv_bfloat162 t = __halves2bfloat162(a, b);   // a -> low half (lower address)
    return *reinterpret_cast<uint32_t*>(&t);
}

__device__ __forceinline__ void ldsm4(uint32_t* r, uint32_t addr) {
    asm volatile("ldmatrix.sync.aligned.m8n8.x4.shared.b16 {%0,%1,%2,%3}, [%4];"
                 : "=r"(r[0]), "=r"(r[1]), "=r"(r[2]), "=r"(r[3]) : "r"(addr));
}
__device__ __forceinline__ void ldsm4t(uint32_t* r, uint32_t addr) {
    asm volatile("ldmatrix.sync.aligned.m8n8.x4.trans.shared.b16 {%0,%1,%2,%3}, [%4];"
                 : "=r"(r[0]), "=r"(r[1]), "=r"(r[2]), "=r"(r[3]) : "r"(addr));
}
__device__ __forceinline__ void mma16816(float* d, const uint32_t* a, const uint32_t* b) {
    asm volatile("mma.sync.aligned.m16n8k16.row.col.f32.bf16.bf16.f32 "
                 "{%0,%1,%2,%3}, {%4,%5,%6,%7}, {%8,%9}, {%0,%1,%2,%3};"
                 : "+f"(d[0]), "+f"(d[1]), "+f"(d[2]), "+f"(d[3])
                 : "r"(a[0]), "r"(a[1]), "r"(a[2]), "r"(a[3]), "r"(b[0]), "r"(b[1]));
}
__device__ __forceinline__ void cp16(uint32_t dst, const void* src) {
    asm volatile("cp.async.cg.shared.global [%0], [%1], 16;" :: "r"(dst), "l"(src));
}
__device__ __forceinline__ void cp_commit() {
    asm volatile("cp.async.commit_group;");
}
template <int N>
__device__ __forceinline__ void cp_wait() {
    asm volatile("cp.async.wait_group %0;" :: "n"(N));
}

// packed f32x2 helpers (sm_103a)
__device__ __forceinline__ unsigned long long pk_f32x2(float lo, float hi) {
    unsigned long long r;
    asm("mov.b64 %0, {%1, %2};" : "=l"(r) : "f"(lo), "f"(hi));
    return r;
}
__device__ __forceinline__ void unpk_f32x2(float& lo, float& hi, unsigned long long v) {
    asm("mov.b64 {%0, %1}, %2;" : "=f"(lo), "=f"(hi) : "l"(v));
}
__device__ __forceinline__ unsigned long long mul_f32x2(unsigned long long a, unsigned long long b) {
    unsigned long long r;
    asm("mul.rn.f32x2 %0, %1, %2;" : "=l"(r) : "l"(a), "l"(b));
    return r;
}
__device__ __forceinline__ void fma_f32x2(unsigned long long& d, unsigned long long a,
                                          unsigned long long b) {
    asm("fma.rn.f32x2 %0, %1, %2, %0;" : "+l"(d) : "l"(a), "l"(b));
}

// smem layout (bytes):
//   Ah: [0, 32768)         32 rows x 512 bf16, chunked: 8 chunks of [32x64], chunk stride 4096,
//                          elem (row,col) at chunk*4096 + swz(row*128 + col*2)
//   Al: [32768, 65536)
//   B stages: [65536, 98304)   stage s (0/1): Bh at 65536+s*16384, Bl at +8192
//                          elem (krow,n) at swz(krow*128 + n*2)
//   cs2: [98304, 104064)   90*8 duplicated f32x2 coeff pairs (8B each)
#define SM_AH 0
#define SM_AL 32768
#define SM_B  65536
#define SM_CS 98304
#define SM_TOTAL 104064

extern __shared__ char smem_raw[];

#define EB 8   // edge batch (MLP depth)

template <bool RELU, int OCOLS>
__global__ void __launch_bounds__(256) fused_layer_kernel(
    const float* __restrict__ x, const float* __restrict__ coeff,
    int layer, const float* __restrict__ bias, float* __restrict__ out) {

    const __nv_bfloat16* Whi = g_Whi[layer];
    const __nv_bfloat16* Wlo = g_Wlo[layer];

    char* sm = smem_raw;
    uint32_t sm_u = (uint32_t)__cvta_generic_to_shared(sm);
    unsigned long long* cs2 = reinterpret_cast<unsigned long long*>(sm + SM_CS);

    int tid = threadIdx.x;
    int wid = tid >> 5, lane = tid & 31;
    int tile0 = blockIdx.x * 32;

    // duplicated coeff pairs -> smem: cs2[r*8+b] = (c, c) as f32x2
    for (int i = tid; i < NREL * NBASES; i += 256) {
        float c = coeff[i];
        cs2[i] = pk_f32x2(c, c);
    }

    // Prefetch B chunk 0 (both planes) into stage 0 while edge phase runs.
    {
        #pragma unroll
        for (int it = 0; it < 4; it++) {
            int u = it * 256 + tid;            // 1024 16B units: 512 hi + 512 lo
            int plane = u >> 9, v = u & 511;
            int row = v >> 3, g = v & 7;
            uint32_t dstb = sm_u + SM_B + plane * 8192 + swz((uint32_t)(row * 128 + g * 16));
            const char* srcb = reinterpret_cast<const char*>(plane ? Wlo : Whi) + row * 128 + g * 16;
            cp16(dstb, srcb);
        }
        cp_commit();
    }
    __syncthreads();   // cs2 visible

    // ---- edge phase: each warp aggregates 4 nodes (static assignment) ----
    // Lane owns features {2*lane, 2*lane+1}. Batch of EB edges: EB packed loads,
    // then EB independent gathers (MLP=EB), then packed-f32x2 FMAs (8 per edge).
    #pragma unroll 1
    for (int t = 0; t < 4; t++) {
        int rt = wid * 4 + t;                  // row within tile 0..31
        int n = tile0 + rt;                    // grid sized so n < NNODES always
        unsigned long long acc2[8];            // (feat 2*lane, 2*lane+1) per basis
        #pragma unroll
        for (int k = 0; k < 8; k++) acc2[k] = 0ULL;
        int s = g_rowptr[n], e = g_rowptr[n + 1];
        #pragma unroll 1
        for (int i = s; i < e; i += EB) {
            unsigned long long p[EB];
            float2 xv[EB];
            #pragma unroll
            for (int k = 0; k < EB; k++)
                p[k] = (i + k < e) ? __ldg(&g_packed[i + k]) : 0ULL;   // p=0 -> nrm=0
            #pragma unroll
            for (int k = 0; k < EB; k++) {
                int srcn = (unsigned)p[k] & 0x1FFFF;
                xv[k] = __ldg(reinterpret_cast<const float2*>(x + (size_t)srcn * 64) + lane);
            }
            #pragma unroll
            for (int k = 0; k < EB; k++) {
                int rel = ((unsigned)p[k] >> 17) & 0x7F;
                float nrm = __uint_as_float((unsigned)(p[k] >> 32));
                unsigned long long x2 = mul_f32x2(pk_f32x2(xv[k].x, xv[k].y),
                                                 pk_f32x2(nrm, nrm));
                const unsigned long long* c2 = cs2 + rel * 8;   // broadcast, conflict-free
                ulonglong2 cA = *reinterpret_cast<const ulonglong2*>(c2);
                ulonglong2 cB = *reinterpret_cast<const ulonglong2*>(c2 + 2);
                ulonglong2 cC = *reinterpret_cast<const ulonglong2*>(c2 + 4);
                ulonglong2 cD = *reinterpret_cast<const ulonglong2*>(c2 + 6);
                fma_f32x2(acc2[0], cA.x, x2);
                fma_f32x2(acc2[1], cA.y, x2);
                fma_f32x2(acc2[2], cB.x, x2);
                fma_f32x2(acc2[3], cB.y, x2);
                fma_f32x2(acc2[4], cC.x, x2);
                fma_f32x2(acc2[5], cC.y, x2);
                fma_f32x2(acc2[6], cD.x, x2);
                fma_f32x2(acc2[7], cD.y, x2);
            }
        }
        // convert to bf16 hi/lo, store pairs (features 2*lane, 2*lane+1 of basis b)
        #pragma unroll
        for (int b = 0; b < 8; b++) {
            float va, vb;
            unpk_f32x2(va, vb, acc2[b]);
            __nv_bfloat16 ha = __float2bfloat16(va);
            __nv_bfloat16 la = __float2bfloat16(va - __bfloat162float(ha));
            __nv_bfloat16 hb = __float2bfloat16(vb);
            __nv_bfloat16 lb = __float2bfloat16(vb - __bfloat162float(hb));
            uint32_t o = (uint32_t)(b * 4096) + swz((uint32_t)(rt * 128 + lane * 4));
            *reinterpret_cast<uint32_t*>(sm + SM_AH + o) = pack2(ha, hb);
            *reinterpret_cast<uint32_t*>(sm + SM_AL + o) = pack2(la, lb);
        }
    }
    __syncthreads();   // A tile complete

    // ---- GEMM phase: [32 x 512] @ [512 x 64], warps 2x4 over 16x16 subtiles ----
    int wm = wid & 1, wn = wid >> 1;
    float facc[2][4];
    #pragma unroll
    for (int a = 0; a < 2; a++)
        #pragma unroll
        for (int b = 0; b < 4; b++) facc[a][b] = 0.0f;

    #pragma unroll 1
    for (int kc8 = 0; kc8 < 8; kc8++) {
        int stage = kc8 & 1;
        if (kc8 < 7) {   // prefetch next chunk into other stage
            int c = kc8 + 1, st = stage ^ 1;
            #pragma unroll
            for (int it = 0; it < 4; it++) {
                int u = it * 256 + tid;
                int plane = u >> 9, v = u & 511;
                int row = v >> 3, g = v & 7;
                uint32_t dstb = sm_u + SM_B + st * 16384 + plane * 8192 +
                                swz((uint32_t)(row * 128 + g * 16));
                const char* srcb = reinterpret_cast<const char*>(plane ? Wlo : Whi) +
                                   (size_t)(c * 64 + row) * 128 + g * 16;
                cp16(dstb, srcb);
            }
            cp_commit();
            cp_wait<1>();
        } else {
            cp_wait<0>();
        }
        __syncthreads();  // current stage data visible to all

        if (OCOLS == 64 || wn == 0) {
            uint32_t uBh = sm_u + SM_B + stage * 16384;
            uint32_t uBl = uBh + 8192;
            #pragma unroll
            for (int ks = 0; ks < 4; ks++) {
                uint32_t ah[4], al[4], bh[4], bl[4];
                int r = wm * 16 + (lane & 15);
                uint32_t oA = (uint32_t)(kc8 * 4096) +
                              swz((uint32_t)(r * 128 + ks * 32 + (lane >> 4) * 16));
                ldsm4(ah, sm_u + SM_AH + oA);
                ldsm4(al, sm_u + SM_AL + oA);
                int mat = lane >> 3, sub = lane & 7;
                int krow = ks * 16 + (mat & 1) * 8 + sub;
                int nb = wn * 16 + (mat >> 1) * 8;
                uint32_t oB = swz((uint32_t)(krow * 128 + nb * 2));
                ldsm4t(bh, uBh + oB);
                ldsm4t(bl, uBl + oB);
                #pragma unroll
                for (int nt = 0; nt < 2; nt++) {
                    float* d = facc[nt];
                    mma16816(d, ah, &bh[nt * 2]);   // hi*hi
                    mma16816(d, ah, &bl[nt * 2]);   // hi*lo
                    mma16816(d, al, &bh[nt * 2]);   // lo*hi
                }
            }
        }
        __syncthreads();  // done reading this stage before it gets overwritten
    }

    // ---- epilogue ----
    #pragma unroll
    for (int nt = 0; nt < 2; nt++)
        #pragma unroll
        for (int r = 0; r < 4; r++) {
            int row = tile0 + wm * 16 + (lane >> 2) + ((r >> 1) ? 8 : 0);
            int col = wn * 16 + nt * 8 + (lane & 3) * 2 + (r & 1);
            if ((OCOLS == 64 || wn == 0) && col < OCOLS) {
                float v = facc[nt][r] + bias[col];
                if (RELU) v = fmaxf(v, 0.0f);
                out[(size_t)row * OCOLS + col] = v;
            }
        }
}

// ---------------- launcher ---------------------------------------------------
extern "C" void kernel_launch(void* const* d_in, const int* in_sizes, int n_in,
                              void* d_out, int out_size) {
    const float* feats  = (const float*)d_in[0];
    const float* coeff0 = (const float*)d_in[1];
    const float* bases0 = (const float*)d_in[2];
    const float* bias0  = (const float*)d_in[3];
    const float* coeff1 = (const float*)d_in[4];
    const float* bases1 = (const float*)d_in[5];
    const float* bias1  = (const float*)d_in[6];
    const float* coeff2 = (const float*)d_in[7];
    const float* bases2 = (const float*)d_in[8];
    const float* bias2  = (const float*)d_in[9];
    const int*   src    = (const int*)d_in[10];
    const int*   dst    = (const int*)d_in[11];
    const int*   etype  = (const int*)d_in[12];
    const float* norm   = (const float*)d_in[13];
    float* out = (float*)d_out;

    cudaFuncSetAttribute(fused_layer_kernel<true, 64>,
                         cudaFuncAttributeMaxDynamicSharedMemorySize, SM_TOTAL);
    cudaFuncSetAttribute(fused_layer_kernel<false, 16>,
                         cudaFuncAttributeMaxDynamicSharedMemorySize, SM_TOTAL);

    // Graph preprocessing (CSR by dst) + weight conversion
    zero_kernel<<<(NNODES + 255) / 256, 256>>>();
    hist_kernel<<<(NEDGES + 255) / 256, 256>>>(dst);
    scan1_kernel<<<NSCANB, 1024>>>();
    scan2_kernel<<<1, 128>>>();
    scan3_kernel<<<(NNODES + 255) / 256, 256>>>();
    scatter_kernel<<<(NEDGES + 255) / 256, 256>>>(src, dst, etype, norm);
    wconv_kernel<<<(3 * KDIM * 64 + 255) / 256, 256>>>(bases0, bases1, bases2);

    // pointers to ping-pong device globals (resolved at launch via symbol refs)
    float* h0;  cudaGetSymbolAddress((void**)&h0, g_h0);
    float* h1;  cudaGetSymbolAddress((void**)&h1, g_h1);

    const int GRID = NNODES / 32;   // 100000/32 = 3125, exact

    // Ping-pong buffers: fused kernels gather-read the previous layer's
    // activations while writing the current layer's — they MUST be distinct
    // (cross-block RAW hazard otherwise).
    fused_layer_kernel<true, 64><<<GRID, 256, SM_TOTAL>>>(feats, coeff0, 0, bias0, h0);
    fused_layer_kernel<true, 64><<<GRID, 256, SM_TOTAL>>>(h0,    coeff1, 1, bias1, h1);
    fused_layer_kernel<false, 16><<<GRID, 256, SM_TOTAL>>>(h1,   coeff2, 2, bias2, out);
}

// round 13
// speedup vs baseline: 1.3905x; 1.1537x over previous
#include <cuda_runtime.h>
#include <cuda_bf16.h>
#include <cstdint>

#define NNODES 100000
#define NEDGES 1000000
#define HDIM   64
#define ODIM   16
#define NREL   90
#define NBASES 8
#define KDIM   512   // NBASES*HDIM
#define NSCANB 98    // ceil(NNODES/1024)

// ---------------- scratch (device globals; no allocations allowed) ----------
__device__ __align__(16) float g_h0[(size_t)NNODES * HDIM];    // ping
__device__ __align__(16) float g_h1[(size_t)NNODES * HDIM];    // pong
__device__ int g_deg[NNODES];
__device__ int g_cursor[NNODES];
__device__ int g_rowptr[NNODES + 1];
__device__ int g_bsum[NSCANB];
__device__ unsigned long long g_packed[NEDGES];                // (norm<<32)|(etype<<17)|src
__device__ __align__(16) __nv_bfloat16 g_Whi[3][KDIM * 64];    // padded to 64 cols
__device__ __align__(16) __nv_bfloat16 g_Wlo[3][KDIM * 64];

// ---------------- preprocessing kernels -------------------------------------
__global__ void zero_kernel() {
    int i = blockIdx.x * blockDim.x + threadIdx.x;
    if (i < NNODES) { g_deg[i] = 0; g_cursor[i] = 0; }
}

__global__ void hist_kernel(const int* __restrict__ dst) {
    int i = blockIdx.x * blockDim.x + threadIdx.x;
    if (i < NEDGES) atomicAdd(&g_deg[dst[i]], 1);
}

// Multi-block scan, pass 1: per-block exclusive scan of 1024 degs + block sum.
__global__ void scan1_kernel() {
    __shared__ int wsum[32];
    int t = threadIdx.x;
    int i = blockIdx.x * 1024 + t;
    int v = (i < NNODES) ? g_deg[i] : 0;
    int x = v;
    #pragma unroll
    for (int o = 1; o < 32; o <<= 1) {
        int y = __shfl_up_sync(0xffffffffu, x, o);
        if ((t & 31) >= o) x += y;
    }
    if ((t & 31) == 31) wsum[t >> 5] = x;
    __syncthreads();
    if (t < 32) {
        int s = wsum[t];
        #pragma unroll
        for (int o = 1; o < 32; o <<= 1) {
            int y = __shfl_up_sync(0xffffffffu, s, o);
            if (t >= o) s += y;
        }
        wsum[t] = s;
    }
    __syncthreads();
    int pre = (t >= 32) ? wsum[(t >> 5) - 1] : 0;
    if (i < NNODES) g_rowptr[i] = pre + x - v;       // block-local exclusive
    if (t == 0) g_bsum[blockIdx.x] = wsum[31];
}

// Pass 2: exclusive scan of the 98 block sums (single small block); writes total.
__global__ void scan2_kernel() {
    __shared__ int wsum[4];
    int t = threadIdx.x;                              // 128 threads
    int v = (t < NSCANB) ? g_bsum[t] : 0;
    int x = v;
    #pragma unroll
    for (int o = 1; o < 32; o <<= 1) {
        int y = __shfl_up_sync(0xffffffffu, x, o);
        if ((t & 31) >= o) x += y;
    }
    if ((t & 31) == 31) wsum[t >> 5] = x;
    __syncthreads();
    if (t < 4) {
        int s = wsum[t];
        #pragma unroll
        for (int o = 1; o < 4; o <<= 1) {
            int y = __shfl_up_sync(0xfu, s, o);
            if (t >= o) s += y;
        }
        wsum[t] = s;
    }
    __syncthreads();
    int pre = (t >= 32) ? wsum[(t >> 5) - 1] : 0;
    if (t < NSCANB) g_bsum[t] = pre + x - v;          // exclusive block offset
    if (t == 0) g_rowptr[NNODES] = wsum[3];           // total = NEDGES
}

// Pass 3: add block offsets.
__global__ void scan3_kernel() {
    int i = blockIdx.x * blockDim.x + threadIdx.x;
    if (i < NNODES) g_rowptr[i] += g_bsum[i >> 10];
}

__global__ void scatter_kernel(const int* __restrict__ src, const int* __restrict__ dst,
                               const int* __restrict__ etype, const float* __restrict__ norm) {
    int i = blockIdx.x * blockDim.x + threadIdx.x;
    if (i >= NEDGES) return;
    int d = dst[i];
    int pos = g_rowptr[d] + atomicAdd(&g_cursor[d], 1);
    unsigned lo = (unsigned)src[i] | ((unsigned)etype[i] << 17);
    g_packed[pos] = ((unsigned long long)__float_as_uint(norm[i]) << 32) | (unsigned long long)lo;
}

// Convert layer weight matrices to bf16 hi/lo split, padded to 64 output cols.
__global__ void wconv_kernel(const float* __restrict__ b0, const float* __restrict__ b1,
                             const float* __restrict__ b2) {
    int i = blockIdx.x * blockDim.x + threadIdx.x;
    if (i >= 3 * KDIM * 64) return;
    int layer = i / (KDIM * 64);
    int r = i % (KDIM * 64);
    int k = r >> 6, j = r & 63;
    float v;
    if (layer == 0)      v = b0[k * 64 + j];
    else if (layer == 1) v = b1[k * 64 + j];
    else                 v = (j < ODIM) ? b2[k * ODIM + j] : 0.0f;
    __nv_bfloat16 hi = __float2bfloat16(v);
    __nv_bfloat16 lo = __float2bfloat16(v - __bfloat162float(hi));
    g_Whi[layer][r] = hi;
    g_Wlo[layer][r] = lo;
}

// ---------------- fused layer: agg (registers) -> smem bf16 -> MMA ----------
__device__ __forceinline__ uint32_t swz(uint32_t o) { return o ^ ((o >> 3) & 0x70); }

__device__ __forceinline__ uint32_t pack2(__nv_bfloat16 a, __nv_bfloat16 b) {
    __nv_bfloat162 t = __halves2bfloat162(a, b);   // a -> low half (lower address)
    return *reinterpret_cast<uint32_t*>(&t);
}

__device__ __forceinline__ void ldsm4(uint32_t* r, uint32_t addr) {
    asm volatile("ldmatrix.sync.aligned.m8n8.x4.shared.b16 {%0,%1,%2,%3}, [%4];"
                 : "=r"(r[0]), "=r"(r[1]), "=r"(r[2]), "=r"(r[3]) : "r"(addr));
}
__device__ __forceinline__ void ldsm4t(uint32_t* r, uint32_t addr) {
    asm volatile("ldmatrix.sync.aligned.m8n8.x4.trans.shared.b16 {%0,%1,%2,%3}, [%4];"
                 : "=r"(r[0]), "=r"(r[1]), "=r"(r[2]), "=r"(r[3]) : "r"(addr));
}
__device__ __forceinline__ void mma16816(float* d, const uint32_t* a, const uint32_t* b) {
    asm volatile("mma.sync.aligned.m16n8k16.row.col.f32.bf16.bf16.f32 "
                 "{%0,%1,%2,%3}, {%4,%5,%6,%7}, {%8,%9}, {%0,%1,%2,%3};"
                 : "+f"(d[0]), "+f"(d[1]), "+f"(d[2]), "+f"(d[3])
                 : "r"(a[0]), "r"(a[1]), "r"(a[2]), "r"(a[3]), "r"(b[0]), "r"(b[1]));
}
__device__ __forceinline__ void cp16(uint32_t dst, const void* src) {
    asm volatile("cp.async.cg.shared.global [%0], [%1], 16;" :: "r"(dst), "l"(src));
}
__device__ __forceinline__ void cp_commit() {
    asm volatile("cp.async.commit_group;");
}
template <int N>
__device__ __forceinline__ void cp_wait() {
    asm volatile("cp.async.wait_group %0;" :: "n"(N));
}

// packed f32x2 helpers (sm_103a)
__device__ __forceinline__ unsigned long long pk_f32x2(float lo, float hi) {
    unsigned long long r;
    asm("mov.b64 %0, {%1, %2};" : "=l"(r) : "f"(lo), "f"(hi));
    return r;
}
__device__ __forceinline__ void unpk_f32x2(float& lo, float& hi, unsigned long long v) {
    asm("mov.b64 {%0, %1}, %2;" : "=f"(lo), "=f"(hi) : "l"(v));
}
__device__ __forceinline__ unsigned long long mul_f32x2(unsigned long long a, unsigned long long b) {
    unsigned long long r;
    asm("mul.rn.f32x2 %0, %1, %2;" : "=l"(r) : "l"(a), "l"(b));
    return r;
}
__device__ __forceinline__ void fma_f32x2(unsigned long long& d, unsigned long long a,
                                          unsigned long long b) {
    asm("fma.rn.f32x2 %0, %1, %2, %0;" : "+l"(d) : "l"(a), "l"(b));
}

// smem layout (bytes):
//   Ah: [0, 32768)         32 rows x 512 bf16, chunked: 8 chunks of [32x64], chunk stride 4096,
//                          elem (row,col) at chunk*4096 + swz(row*128 + col*2)
//   Al: [32768, 65536)
//   B stages: [65536, 98304)   stage s (0/1): Bh at 65536+s*16384, Bl at +8192
//                          elem (krow,n) at swz(krow*128 + n*2)
//   cs2: [98304, 104064)   90*8 duplicated f32x2 coeff pairs (8B each)
#define SM_AH 0
#define SM_AL 32768
#define SM_B  65536
#define SM_CS 98304
#define SM_TOTAL 104064

extern __shared__ char smem_raw[];

#define EB 8   // edge batch (MLP depth)

template <bool RELU, int OCOLS>
__global__ void __launch_bounds__(256, 2) fused_layer_kernel(
    const float* __restrict__ x, const float* __restrict__ coeff,
    int layer, const float* __restrict__ bias, float* __restrict__ out) {

    const __nv_bfloat16* Whi = g_Whi[layer];
    const __nv_bfloat16* Wlo = g_Wlo[layer];

    char* sm = smem_raw;
    uint32_t sm_u = (uint32_t)__cvta_generic_to_shared(sm);
    unsigned long long* cs2 = reinterpret_cast<unsigned long long*>(sm + SM_CS);

    int tid = threadIdx.x;
    int wid = tid >> 5, lane = tid & 31;
    int tile0 = blockIdx.x * 32;

    // duplicated coeff pairs -> smem: cs2[r*8+b] = (c, c) as f32x2
    for (int i = tid; i < NREL * NBASES; i += 256) {
        float c = coeff[i];
        cs2[i] = pk_f32x2(c, c);
    }

    // Prefetch B chunk 0 (both planes) into stage 0 while edge phase runs.
    {
        #pragma unroll
        for (int it = 0; it < 4; it++) {
            int u = it * 256 + tid;            // 1024 16B units: 512 hi + 512 lo
            int plane = u >> 9, v = u & 511;
            int row = v >> 3, g = v & 7;
            uint32_t dstb = sm_u + SM_B + plane * 8192 + swz((uint32_t)(row * 128 + g * 16));
            const char* srcb = reinterpret_cast<const char*>(plane ? Wlo : Whi) + row * 128 + g * 16;
            cp16(dstb, srcb);
        }
        cp_commit();
    }
    __syncthreads();   // cs2 visible

    // ---- edge phase: each warp aggregates 4 nodes (static assignment) ----
    // Lane owns features {2*lane, 2*lane+1}. Batch of EB edges: EB packed loads,
    // then EB independent gathers (MLP=EB), then packed-f32x2 FMAs (8 per edge).
    #pragma unroll 1
    for (int t = 0; t < 4; t++) {
        int rt = wid * 4 + t;                  // row within tile 0..31
        int n = tile0 + rt;                    // grid sized so n < NNODES always
        unsigned long long acc2[8];            // (feat 2*lane, 2*lane+1) per basis
        #pragma unroll
        for (int k = 0; k < 8; k++) acc2[k] = 0ULL;
        int s = g_rowptr[n], e = g_rowptr[n + 1];
        #pragma unroll 1
        for (int i = s; i < e; i += EB) {
            unsigned long long p[EB];
            float2 xv[EB];
            #pragma unroll
            for (int k = 0; k < EB; k++)
                p[k] = (i + k < e) ? __ldg(&g_packed[i + k]) : 0ULL;   // p=0 -> nrm=0
            #pragma unroll
            for (int k = 0; k < EB; k++) {
                int srcn = (unsigned)p[k] & 0x1FFFF;
                xv[k] = __ldg(reinterpret_cast<const float2*>(x + (size_t)srcn * 64) + lane);
            }
            #pragma unroll
            for (int k = 0; k < EB; k++) {
                int rel = ((unsigned)p[k] >> 17) & 0x7F;
                float nrm = __uint_as_float((unsigned)(p[k] >> 32));
                unsigned long long x2 = mul_f32x2(pk_f32x2(xv[k].x, xv[k].y),
                                                 pk_f32x2(nrm, nrm));
                const unsigned long long* c2 = cs2 + rel * 8;   // broadcast, conflict-free
                ulonglong2 cA = *reinterpret_cast<const ulonglong2*>(c2);
                ulonglong2 cB = *reinterpret_cast<const ulonglong2*>(c2 + 2);
                ulonglong2 cC = *reinterpret_cast<const ulonglong2*>(c2 + 4);
                ulonglong2 cD = *reinterpret_cast<const ulonglong2*>(c2 + 6);
                fma_f32x2(acc2[0], cA.x, x2);
                fma_f32x2(acc2[1], cA.y, x2);
                fma_f32x2(acc2[2], cB.x, x2);
                fma_f32x2(acc2[3], cB.y, x2);
                fma_f32x2(acc2[4], cC.x, x2);
                fma_f32x2(acc2[5], cC.y, x2);
                fma_f32x2(acc2[6], cD.x, x2);
                fma_f32x2(acc2[7], cD.y, x2);
            }
        }
        // convert to bf16 hi/lo, store pairs (features 2*lane, 2*lane+1 of basis b)
        #pragma unroll
        for (int b = 0; b < 8; b++) {
            float va, vb;
            unpk_f32x2(va, vb, acc2[b]);
            __nv_bfloat16 ha = __float2bfloat16(va);
            __nv_bfloat16 la = __float2bfloat16(va - __bfloat162float(ha));
            __nv_bfloat16 hb = __float2bfloat16(vb);
            __nv_bfloat16 lb = __float2bfloat16(vb - __bfloat162float(hb));
            uint32_t o = (uint32_t)(b * 4096) + swz((uint32_t)(rt * 128 + lane * 4));
            *reinterpret_cast<uint32_t*>(sm + SM_AH + o) = pack2(ha, hb);
            *reinterpret_cast<uint32_t*>(sm + SM_AL + o) = pack2(la, lb);
        }
    }
    __syncthreads();   // A tile complete

    // ---- GEMM phase: [32 x 512] @ [512 x 64], warps 2x4 over 16x16 subtiles ----
    int wm = wid & 1, wn = wid >> 1;
    float facc[2][4];
    #pragma unroll
    for (int a = 0; a < 2; a++)
        #pragma unroll
        for (int b = 0; b < 4; b++) facc[a][b] = 0.0f;

    #pragma unroll 1
    for (int kc8 = 0; kc8 < 8; kc8++) {
        int stage = kc8 & 1;
        if (kc8 < 7) {   // prefetch next chunk into other stage
            int c = kc8 + 1, st = stage ^ 1;
            #pragma unroll
            for (int it = 0; it < 4; it++) {
                int u = it * 256 + tid;
                int plane = u >> 9, v = u & 511;
                int row = v >> 3, g = v & 7;
                uint32_t dstb = sm_u + SM_B + st * 16384 + plane * 8192 +
                                swz((uint32_t)(row * 128 + g * 16));
                const char* srcb = reinterpret_cast<const char*>(plane ? Wlo : Whi) +
                                   (size_t)(c * 64 + row) * 128 + g * 16;
                cp16(dstb, srcb);
            }
            cp_commit();
            cp_wait<1>();
        } else {
            cp_wait<0>();
        }
        __syncthreads();  // current stage data visible to all

        if (OCOLS == 64 || wn == 0) {
            uint32_t uBh = sm_u + SM_B + stage * 16384;
            uint32_t uBl = uBh + 8192;
            #pragma unroll
            for (int ks = 0; ks < 4; ks++) {
                uint32_t ah[4], al[4], bh[4], bl[4];
                int r = wm * 16 + (lane & 15);
                uint32_t oA = (uint32_t)(kc8 * 4096) +
                              swz((uint32_t)(r * 128 + ks * 32 + (lane >> 4) * 16));
                ldsm4(ah, sm_u + SM_AH + oA);
                ldsm4(al, sm_u + SM_AL + oA);
                int mat = lane >> 3, sub = lane & 7;
                int krow = ks * 16 + (mat & 1) * 8 + sub;
                int nb = wn * 16 + (mat >> 1) * 8;
                uint32_t oB = swz((uint32_t)(krow * 128 + nb * 2));
                ldsm4t(bh, uBh + oB);
                ldsm4t(bl, uBl + oB);
                #pragma unroll
                for (int nt = 0; nt < 2; nt++) {
                    float* d = facc[nt];
                    mma16816(d, ah, &bh[nt * 2]);   // hi*hi
                    mma16816(d, ah, &bl[nt * 2]);   // hi*lo
                    mma16816(d, al, &bh[nt * 2]);   // lo*hi
                }
            }
        }
        __syncthreads();  // done reading this stage before it gets overwritten
    }

    // ---- epilogue ----
    #pragma unroll
    for (int nt = 0; nt < 2; nt++)
        #pragma unroll
        for (int r = 0; r < 4; r++) {
            int row = tile0 + wm * 16 + (lane >> 2) + ((r >> 1) ? 8 : 0);
            int col = wn * 16 + nt * 8 + (lane & 3) * 2 + (r & 1);
            if ((OCOLS == 64 || wn == 0) && col < OCOLS) {
                float v = facc[nt][r] + bias[col];
                if (RELU) v = fmaxf(v, 0.0f);
                out[(size_t)row * OCOLS + col] = v;
            }
        }
}

// ---------------- launcher ---------------------------------------------------
extern "C" void kernel_launch(void* const* d_in, const int* in_sizes, int n_in,
                              void* d_out, int out_size) {
    const float* feats  = (const float*)d_in[0];
    const float* coeff0 = (const float*)d_in[1];
    const float* bases0 = (const float*)d_in[2];
    const float* bias0  = (const float*)d_in[3];
    const float* coeff1 = (const float*)d_in[4];
    const float* bases1 = (const float*)d_in[5];
    const float* bias1  = (const float*)d_in[6];
    const float* coeff2 = (const float*)d_in[7];
    const float* bases2 = (const float*)d_in[8];
    const float* bias2  = (const float*)d_in[9];
    const int*   src    = (const int*)d_in[10];
    const int*   dst    = (const int*)d_in[11];
    const int*   etype  = (const int*)d_in[12];
    const float* norm   = (const float*)d_in[13];
    float* out = (float*)d_out;

    cudaFuncSetAttribute(fused_layer_kernel<true, 64>,
                         cudaFuncAttributeMaxDynamicSharedMemorySize, SM_TOTAL);
    cudaFuncSetAttribute(fused_layer_kernel<false, 16>,
                         cudaFuncAttributeMaxDynamicSharedMemorySize, SM_TOTAL);

    // Graph preprocessing (CSR by dst) + weight conversion
    zero_kernel<<<(NNODES + 255) / 256, 256>>>();
    hist_kernel<<<(NEDGES + 255) / 256, 256>>>(dst);
    scan1_kernel<<<NSCANB, 1024>>>();
    scan2_kernel<<<1, 128>>>();
    scan3_kernel<<<(NNODES + 255) / 256, 256>>>();
    scatter_kernel<<<(NEDGES + 255) / 256, 256>>>(src, dst, etype, norm);
    wconv_kernel<<<(3 * KDIM * 64 + 255) / 256, 256>>>(bases0, bases1, bases2);

    // pointers to ping-pong device globals (resolved at launch via symbol refs)
    float* h0;  cudaGetSymbolAddress((void**)&h0, g_h0);
    float* h1;  cudaGetSymbolAddress((void**)&h1, g_h1);

    const int GRID = NNODES / 32;   // 100000/32 = 3125, exact

    // Ping-pong buffers: fused kernels gather-read the previous layer's
    // activations while writing the current layer's — they MUST be distinct
    // (cross-block RAW hazard otherwise).
    fused_layer_kernel<true, 64><<<GRID, 256, SM_TOTAL>>>(feats, coeff0, 0, bias0, h0);
    fused_layer_kernel<true, 64><<<GRID, 256, SM_TOTAL>>>(h0,    coeff1, 1, bias1, h1);
    fused_layer_kernel<false, 16><<<GRID, 256, SM_TOTAL>>>(h1,   coeff2, 2, bias2, out);
}